// round 2
// baseline (speedup 1.0000x reference)
#include <cuda_runtime.h>

#define NN 100000
#define EE 1600000
#define DD 64
#define FEPS 1e-9f

// ---------------- scratch (static device memory; no allocations) ----------------
__device__ float g_h [NN*DD];
__device__ float g_m0[NN*DD];
__device__ float g_m1[NN*DD];
__device__ float g_m2[NN*DD];
__device__ float g_m3[NN*DD];
__device__ int   g_deg[NN];

// ---------------- helpers ----------------
__device__ __forceinline__ void red_add4(float* p, float4 v) {
    asm volatile("red.global.add.v4.f32 [%0], {%1, %2, %3, %4};"
                 :: "l"(p), "f"(v.x), "f"(v.y), "f"(v.z), "f"(v.w) : "memory");
}

// a*X + b*(Y - Z)
__device__ __forceinline__ float4 comb4(float a, float4 X, float b, float4 Y, float4 Z) {
    float4 r;
    r.x = a*X.x + b*(Y.x - Z.x);
    r.y = a*X.y + b*(Y.y - Z.y);
    r.z = a*X.z + b*(Y.z - Z.z);
    r.w = a*X.w + b*(Y.w - Z.w);
    return r;
}

__device__ __forceinline__ float4 ld4(const float* p) { return *(const float4*)p; }

// ---------------- kernels ----------------

// Zero accumulators + degree counters (replay-safe: runs every launch).
__global__ void zero_kernel() {
    int idx = blockIdx.x * blockDim.x + threadIdx.x;
    const int tot4 = NN * DD / 4;   // 1.6M float4 per array
    if (idx < tot4) {
        float4 z = make_float4(0.f, 0.f, 0.f, 0.f);
        ((float4*)g_m0)[idx] = z;
        ((float4*)g_m1)[idx] = z;
        ((float4*)g_m2)[idx] = z;
        ((float4*)g_m3)[idx] = z;
    }
    if (idx < NN) g_deg[idx] = 0;
}

__global__ void deg_kernel(const int* __restrict__ src) {
    int e = blockIdx.x * blockDim.x + threadIdx.x;
    if (e < EE) atomicAdd(&g_deg[src[e]], 1);
}

// h = x @ W + b   (100000 x 64) @ (64 x 64). smem-staged, 32 rows/block.
__global__ __launch_bounds__(256) void gemm_kernel(
    const float* __restrict__ x, const float* __restrict__ W, const float* __restrict__ b)
{
    __shared__ float sW[64 * 64];
    __shared__ float sx[32 * 68];   // row stride 68 floats (272B, 16B-aligned, bank-spread)
    __shared__ float sb[64];
    int t = threadIdx.x;
    #pragma unroll
    for (int i = t; i < 4096; i += 256) sW[i] = W[i];
    if (t < 64) sb[t] = b[t];
    int row0 = blockIdx.x * 32;
    const float4* xv = (const float4*)(x + row0 * 64);
    #pragma unroll
    for (int i = t; i < 512; i += 256) {     // 32 rows * 16 float4
        float4 v = xv[i];
        int r = i >> 4, c4 = i & 15;
        float* d = &sx[r * 68 + c4 * 4];
        d[0] = v.x; d[1] = v.y; d[2] = v.z; d[3] = v.w;
    }
    __syncthreads();
    int r = t >> 3, c0 = (t & 7) * 8;        // 8 threads per row, 8 cols each
    float acc[8];
    #pragma unroll
    for (int j = 0; j < 8; j++) acc[j] = sb[c0 + j];
    #pragma unroll
    for (int k = 0; k < 64; k++) {
        float xk = sx[r * 68 + k];
        float4 w0 = *(const float4*)&sW[k * 64 + c0];
        float4 w1 = *(const float4*)&sW[k * 64 + c0 + 4];
        acc[0] += xk * w0.x; acc[1] += xk * w0.y; acc[2] += xk * w0.z; acc[3] += xk * w0.w;
        acc[4] += xk * w1.x; acc[5] += xk * w1.y; acc[6] += xk * w1.z; acc[7] += xk * w1.w;
    }
    float* out = &g_h[(row0 + r) * 64 + c0];
    *(float4*)out       = make_float4(acc[0], acc[1], acc[2], acc[3]);
    *(float4*)(out + 4) = make_float4(acc[4], acc[5], acc[6], acc[7]);
}

// m0[v] += h[u]   (16 threads per edge, float4 each)
__global__ __launch_bounds__(256) void pass0_kernel(
    const int* __restrict__ src, const int* __restrict__ dst)
{
    int tid = blockIdx.x * blockDim.x + threadIdx.x;
    int e = tid >> 4;
    if (e >= EE) return;
    int c = (tid & 15) * 4;
    int u = src[e], v = dst[e];
    float4 hu = ld4(g_h + u * 64 + c);
    red_add4(g_m0 + v * 64 + c, hu);
}

// m1[v] += M1[e],  M1 = du==1 ? h[u] : (1-l)h[u] + cu*(m0[u]-h[v])
__global__ __launch_bounds__(256) void pass1_kernel(
    const int* __restrict__ src, const int* __restrict__ dst, const float* __restrict__ lptr)
{
    int tid = blockIdx.x * blockDim.x + threadIdx.x;
    int e = tid >> 4;
    if (e >= EE) return;
    int c = (tid & 15) * 4;
    float lm = __ldg(lptr);
    int u = src[e], v = dst[e];
    int du = g_deg[u];
    float4 hu = ld4(g_h + u * 64 + c);
    float4 r;
    if (du == 1) {
        r = hu;
    } else {
        float cu = lm / ((float)du - 1.0f + FEPS);
        float4 hv  = ld4(g_h  + v * 64 + c);
        float4 m0u = ld4(g_m0 + u * 64 + c);
        r = comb4(1.0f - lm, hu, cu, m0u, hv);
    }
    red_add4(g_m1 + v * 64 + c, r);
}

// m2[v] += M2[e],  M2 = du==1 ? h[u] : (1-l)h[u] + cu*(m1[u] - M1[rev e])
//   M1[rev e] = dv==1 ? h[v] : (1-l)h[v] + cv*(m0[v]-h[u])
__global__ __launch_bounds__(256) void pass2_kernel(
    const int* __restrict__ src, const int* __restrict__ dst, const float* __restrict__ lptr)
{
    int tid = blockIdx.x * blockDim.x + threadIdx.x;
    int e = tid >> 4;
    if (e >= EE) return;
    int c = (tid & 15) * 4;
    float lm = __ldg(lptr);
    int u = src[e], v = dst[e];
    int du = g_deg[u];
    float4 hu = ld4(g_h + u * 64 + c);
    float4 r;
    if (du == 1) {
        r = hu;
    } else {
        float4 hv = ld4(g_h + v * 64 + c);
        int dv = g_deg[v];
        float4 M1r;
        if (dv == 1) {
            M1r = hv;
        } else {
            float cv = lm / ((float)dv - 1.0f + FEPS);
            float4 m0v = ld4(g_m0 + v * 64 + c);
            M1r = comb4(1.0f - lm, hv, cv, m0v, hu);
        }
        float cu = lm / ((float)du - 1.0f + FEPS);
        float4 m1u = ld4(g_m1 + u * 64 + c);
        r = comb4(1.0f - lm, hu, cu, m1u, M1r);
    }
    red_add4(g_m2 + v * 64 + c, r);
}

// m3[v] += M3[e],  M3 = du==1 ? h[u] : (1-l)h[u] + cu*(m2[u] - M2[rev e])
//   M2[rev e] = dv==1 ? h[v] : (1-l)h[v] + cv*(m1[v] - M1[e])
//   M1[e]     = (du!=1 here) (1-l)h[u] + cu*(m0[u]-h[v])
__global__ __launch_bounds__(256) void pass3_kernel(
    const int* __restrict__ src, const int* __restrict__ dst, const float* __restrict__ lptr)
{
    int tid = blockIdx.x * blockDim.x + threadIdx.x;
    int e = tid >> 4;
    if (e >= EE) return;
    int c = (tid & 15) * 4;
    float lm = __ldg(lptr);
    int u = src[e], v = dst[e];
    int du = g_deg[u];
    float4 hu = ld4(g_h + u * 64 + c);
    float4 r;
    if (du == 1) {
        r = hu;
    } else {
        float cu = lm / ((float)du - 1.0f + FEPS);
        float4 hv = ld4(g_h + v * 64 + c);
        int dv = g_deg[v];
        float4 M2r;
        if (dv == 1) {
            M2r = hv;
        } else {
            float cv = lm / ((float)dv - 1.0f + FEPS);
            float4 m0u = ld4(g_m0 + u * 64 + c);
            float4 M1e = comb4(1.0f - lm, hu, cu, m0u, hv);   // du != 1 in this branch
            float4 m1v = ld4(g_m1 + v * 64 + c);
            M2r = comb4(1.0f - lm, hv, cv, m1v, M1e);
        }
        float4 m2u = ld4(g_m2 + u * 64 + c);
        r = comb4(1.0f - lm, hu, cu, m2u, M2r);
    }
    red_add4(g_m3 + v * 64 + c, r);
}

// out = x + relu( deg==0 ? h : (1-l)h + l/(deg+eps)*m3 )
__global__ __launch_bounds__(256) void final_kernel(
    const float* __restrict__ x, const float* __restrict__ lptr, float* __restrict__ out)
{
    int i = blockIdx.x * blockDim.x + threadIdx.x;   // one float4 per thread
    const int tot4 = NN * DD / 4;
    if (i >= tot4) return;
    float lm = __ldg(lptr);
    int n = i >> 4;
    int d = g_deg[n];
    float4 h = ((const float4*)g_h)[i];
    float4 r;
    if (d == 0) {
        r = h;
    } else {
        float s = lm / ((float)d + FEPS);
        float4 m = ((const float4*)g_m3)[i];
        r.x = (1.0f - lm) * h.x + s * m.x;
        r.y = (1.0f - lm) * h.y + s * m.y;
        r.z = (1.0f - lm) * h.z + s * m.z;
        r.w = (1.0f - lm) * h.w + s * m.w;
    }
    r.x = fmaxf(r.x, 0.f); r.y = fmaxf(r.y, 0.f);
    r.z = fmaxf(r.z, 0.f); r.w = fmaxf(r.w, 0.f);
    float4 xv = ((const float4*)x)[i];
    ((float4*)out)[i] = make_float4(xv.x + r.x, xv.y + r.y, xv.z + r.z, xv.w + r.w);
}

// ---------------- launch ----------------
extern "C" void kernel_launch(void* const* d_in, const int* in_sizes, int n_in,
                              void* d_out, int out_size)
{
    const float* x  = (const float*)d_in[0];
    const int*   ei = (const int*)  d_in[1];
    const float* W  = (const float*)d_in[2];
    const float* b  = (const float*)d_in[3];
    const float* lm = (const float*)d_in[4];
    const int* src = ei;
    const int* dst = ei + EE;

    const int edgeBlocks = (EE * 16) / 256;          // 100000
    zero_kernel<<<(NN * DD / 4 + 255) / 256, 256>>>();
    deg_kernel<<<(EE + 255) / 256, 256>>>(src);
    gemm_kernel<<<NN / 32, 256>>>(x, W, b);
    pass0_kernel<<<edgeBlocks, 256>>>(src, dst);
    pass1_kernel<<<edgeBlocks, 256>>>(src, dst, lm);
    pass2_kernel<<<edgeBlocks, 256>>>(src, dst, lm);
    pass3_kernel<<<edgeBlocks, 256>>>(src, dst, lm);
    final_kernel<<<(NN * DD / 4 + 255) / 256, 256>>>(x, lm, (float*)d_out);
}

// round 3
// speedup vs baseline: 1.5526x; 1.5526x over previous
#include <cuda_runtime.h>

#define NN 100000
#define EE 1600000
#define FEPS 1e-9f

// ---------------- static device scratch ----------------
__device__ float g_h  [NN * 64];
__device__ float g_P1 [NN * 64];
__device__ float g_P2 [NN * 64];
__device__ float g_P3 [NN * 64];
__device__ float g_q  [NN * 64];   // q[v]  = sum_u beta_u * h[u]
__device__ float g_r  [NN * 64];   // r[v]  = sum_u beta_u * P1[u]
__device__ float g_beta[NN];
__device__ float g_sb  [NN];       // sum_u beta_u
__device__ float g_sb2 [NN];       // sum_u beta_u^2
__device__ int   g_deg [NN];
__device__ int   g_start[NN + 1];
__device__ int   g_cursor[NN];
__device__ int   g_adj[EE];        // in-neighbor (src) list bucketed by dst

__device__ __forceinline__ float2 ld2(const float* p) { return *(const float2*)p; }
__device__ __forceinline__ void   st2(float* p, float2 v) { *(float2*)p = v; }

// ---------------- CSR build ----------------
__global__ void zero_deg_kernel() {
    int i = blockIdx.x * blockDim.x + threadIdx.x;
    if (i < NN) g_deg[i] = 0;
}

__global__ void deg_kernel(const int* __restrict__ src) {
    int e = blockIdx.x * blockDim.x + threadIdx.x;
    if (e < EE) atomicAdd(&g_deg[src[e]], 1);
}

__global__ void beta_kernel(const float* __restrict__ lptr) {
    int i = blockIdx.x * blockDim.x + threadIdx.x;
    if (i >= NN) return;
    float lm = __ldg(lptr);
    int d = g_deg[i];
    g_beta[i] = (d == 1) ? 0.0f : lm / ((float)d - 1.0f + FEPS);
}

// Single-block exclusive scan of deg -> start, cursor
__global__ __launch_bounds__(1024) void scan_kernel() {
    __shared__ int sums[1024];
    int t = threadIdx.x;
    const int per = (NN + 1023) / 1024;  // 98
    int base = t * per;
    int s = 0;
    for (int i = 0; i < per; i++) {
        int idx = base + i;
        if (idx < NN) s += g_deg[idx];
    }
    sums[t] = s;
    __syncthreads();
    // Hillis-Steele inclusive scan
    for (int off = 1; off < 1024; off <<= 1) {
        int v = (t >= off) ? sums[t - off] : 0;
        __syncthreads();
        sums[t] += v;
        __syncthreads();
    }
    int run = sums[t] - s;  // exclusive base for this chunk
    for (int i = 0; i < per; i++) {
        int idx = base + i;
        if (idx < NN) {
            g_start[idx]  = run;
            g_cursor[idx] = run;
            run += g_deg[idx];
        }
    }
    if (t == 1023) g_start[NN] = sums[1023];
}

__global__ void adjfill_kernel(const int* __restrict__ src, const int* __restrict__ dst) {
    int e = blockIdx.x * blockDim.x + threadIdx.x;
    if (e >= EE) return;
    int v = dst[e];
    int pos = atomicAdd(&g_cursor[v], 1);
    g_adj[pos] = src[e];
}

// ---------------- h = x @ W + b ----------------
__global__ __launch_bounds__(256) void gemm_kernel(
    const float* __restrict__ x, const float* __restrict__ W, const float* __restrict__ b)
{
    __shared__ float sW[64 * 64];
    __shared__ float sx[32 * 68];
    __shared__ float sb[64];
    int t = threadIdx.x;
    #pragma unroll
    for (int i = t; i < 4096; i += 256) sW[i] = W[i];
    if (t < 64) sb[t] = b[t];
    int row0 = blockIdx.x * 32;
    const float4* xv = (const float4*)(x + row0 * 64);
    #pragma unroll
    for (int i = t; i < 512; i += 256) {
        float4 v = xv[i];
        int r = i >> 4, c4 = i & 15;
        float* d = &sx[r * 68 + c4 * 4];
        d[0] = v.x; d[1] = v.y; d[2] = v.z; d[3] = v.w;
    }
    __syncthreads();
    int r = t >> 3, c0 = (t & 7) * 8;
    float acc[8];
    #pragma unroll
    for (int j = 0; j < 8; j++) acc[j] = sb[c0 + j];
    #pragma unroll
    for (int k = 0; k < 64; k++) {
        float xk = sx[r * 68 + k];
        float4 w0 = *(const float4*)&sW[k * 64 + c0];
        float4 w1 = *(const float4*)&sW[k * 64 + c0 + 4];
        acc[0] += xk * w0.x; acc[1] += xk * w0.y; acc[2] += xk * w0.z; acc[3] += xk * w0.w;
        acc[4] += xk * w1.x; acc[5] += xk * w1.y; acc[6] += xk * w1.z; acc[7] += xk * w1.w;
    }
    float* out = &g_h[(row0 + r) * 64 + c0];
    *(float4*)out       = make_float4(acc[0], acc[1], acc[2], acc[3]);
    *(float4*)(out + 4) = make_float4(acc[4], acc[5], acc[6], acc[7]);
}

// ---------------- gather passes: one warp per node, float2 per lane ----------------

// G1: m0 = sum h[u]; q = sum b_u h[u]; sb, sb2; P1 = a*h + b*m0
__global__ __launch_bounds__(256) void g1_kernel(const float* __restrict__ lptr) {
    int w = (blockIdx.x * blockDim.x + threadIdx.x) >> 5;
    int lane = threadIdx.x & 31;
    if (w >= NN) return;
    int beg = g_start[w], end = g_start[w + 1];
    float2 s0 = make_float2(0.f, 0.f), s1 = make_float2(0.f, 0.f);
    float sb = 0.f, sb2 = 0.f;
    int j = beg;
    for (; j + 1 < end; j += 2) {
        int u0 = g_adj[j], u1 = g_adj[j + 1];
        float b0 = g_beta[u0], b1 = g_beta[u1];
        float2 h0 = ld2(g_h + u0 * 64 + lane * 2);
        float2 h1 = ld2(g_h + u1 * 64 + lane * 2);
        s0.x += h0.x + h1.x;        s0.y += h0.y + h1.y;
        s1.x += b0 * h0.x + b1 * h1.x; s1.y += b0 * h0.y + b1 * h1.y;
        sb  += b0 + b1;
        sb2 += b0 * b0 + b1 * b1;
    }
    if (j < end) {
        int u0 = g_adj[j];
        float b0 = g_beta[u0];
        float2 h0 = ld2(g_h + u0 * 64 + lane * 2);
        s0.x += h0.x; s0.y += h0.y;
        s1.x += b0 * h0.x; s1.y += b0 * h0.y;
        sb += b0; sb2 += b0 * b0;
    }
    float lm = __ldg(lptr);
    float b = g_beta[w];
    float a = (b == 0.f) ? 1.f : (1.f - lm);
    float2 hv = ld2(g_h + w * 64 + lane * 2);
    float2 P1 = make_float2(a * hv.x + b * s0.x, a * hv.y + b * s0.y);
    st2(g_P1 + w * 64 + lane * 2, P1);
    st2(g_q  + w * 64 + lane * 2, s1);
    if (lane == 0) { g_sb[w] = sb; g_sb2[w] = sb2; }
}

// G2: p1 = sum P1[u]; r = sum b_u P1[u]; m1 = p1 - sb*h; P2 = a*h + b*m1
__global__ __launch_bounds__(256) void g2_kernel(const float* __restrict__ lptr) {
    int w = (blockIdx.x * blockDim.x + threadIdx.x) >> 5;
    int lane = threadIdx.x & 31;
    if (w >= NN) return;
    int beg = g_start[w], end = g_start[w + 1];
    float2 s0 = make_float2(0.f, 0.f), s1 = make_float2(0.f, 0.f);
    int j = beg;
    for (; j + 1 < end; j += 2) {
        int u0 = g_adj[j], u1 = g_adj[j + 1];
        float b0 = g_beta[u0], b1 = g_beta[u1];
        float2 p0 = ld2(g_P1 + u0 * 64 + lane * 2);
        float2 p1v = ld2(g_P1 + u1 * 64 + lane * 2);
        s0.x += p0.x + p1v.x;          s0.y += p0.y + p1v.y;
        s1.x += b0 * p0.x + b1 * p1v.x; s1.y += b0 * p0.y + b1 * p1v.y;
    }
    if (j < end) {
        int u0 = g_adj[j];
        float b0 = g_beta[u0];
        float2 p0 = ld2(g_P1 + u0 * 64 + lane * 2);
        s0.x += p0.x; s0.y += p0.y;
        s1.x += b0 * p0.x; s1.y += b0 * p0.y;
    }
    float lm = __ldg(lptr);
    float b = g_beta[w];
    float a = (b == 0.f) ? 1.f : (1.f - lm);
    float sbv = g_sb[w];
    float2 hv = ld2(g_h + w * 64 + lane * 2);
    float2 m1 = make_float2(s0.x - sbv * hv.x, s0.y - sbv * hv.y);
    float2 P2 = make_float2(a * hv.x + b * m1.x, a * hv.y + b * m1.y);
    st2(g_P2 + w * 64 + lane * 2, P2);
    st2(g_r  + w * 64 + lane * 2, s1);
}

// G3: p2 = sum P2[u]; m2 = p2 + b*q - sb*P1; P3 = a*h + b*m2
__global__ __launch_bounds__(256) void g3_kernel(const float* __restrict__ lptr) {
    int w = (blockIdx.x * blockDim.x + threadIdx.x) >> 5;
    int lane = threadIdx.x & 31;
    if (w >= NN) return;
    int beg = g_start[w], end = g_start[w + 1];
    float2 s0 = make_float2(0.f, 0.f);
    int j = beg;
    for (; j + 1 < end; j += 2) {
        int u0 = g_adj[j], u1 = g_adj[j + 1];
        float2 p0 = ld2(g_P2 + u0 * 64 + lane * 2);
        float2 p1v = ld2(g_P2 + u1 * 64 + lane * 2);
        s0.x += p0.x + p1v.x; s0.y += p0.y + p1v.y;
    }
    if (j < end) {
        int u0 = g_adj[j];
        float2 p0 = ld2(g_P2 + u0 * 64 + lane * 2);
        s0.x += p0.x; s0.y += p0.y;
    }
    float lm = __ldg(lptr);
    float b = g_beta[w];
    float a = (b == 0.f) ? 1.f : (1.f - lm);
    float sbv = g_sb[w];
    float2 hv  = ld2(g_h  + w * 64 + lane * 2);
    float2 qv  = ld2(g_q  + w * 64 + lane * 2);
    float2 P1v = ld2(g_P1 + w * 64 + lane * 2);
    float2 m2 = make_float2(s0.x + b * qv.x - sbv * P1v.x,
                            s0.y + b * qv.y - sbv * P1v.y);
    float2 P3 = make_float2(a * hv.x + b * m2.x, a * hv.y + b * m2.y);
    st2(g_P3 + w * 64 + lane * 2, P3);
}

// G4: p3 = sum P3[u]; m3 = p3 + b*r - sb*P2 - b*sb2*h; out = x + relu(final)
__global__ __launch_bounds__(256) void g4_kernel(
    const float* __restrict__ x, const float* __restrict__ lptr, float* __restrict__ out)
{
    int w = (blockIdx.x * blockDim.x + threadIdx.x) >> 5;
    int lane = threadIdx.x & 31;
    if (w >= NN) return;
    int beg = g_start[w], end = g_start[w + 1];
    float2 s0 = make_float2(0.f, 0.f);
    int j = beg;
    for (; j + 1 < end; j += 2) {
        int u0 = g_adj[j], u1 = g_adj[j + 1];
        float2 p0 = ld2(g_P3 + u0 * 64 + lane * 2);
        float2 p1v = ld2(g_P3 + u1 * 64 + lane * 2);
        s0.x += p0.x + p1v.x; s0.y += p0.y + p1v.y;
    }
    if (j < end) {
        int u0 = g_adj[j];
        float2 p0 = ld2(g_P3 + u0 * 64 + lane * 2);
        s0.x += p0.x; s0.y += p0.y;
    }
    float lm = __ldg(lptr);
    float b = g_beta[w];
    float sbv = g_sb[w], sb2v = g_sb2[w];
    float2 hv  = ld2(g_h  + w * 64 + lane * 2);
    float2 rv  = ld2(g_r  + w * 64 + lane * 2);
    float2 P2v = ld2(g_P2 + w * 64 + lane * 2);
    float2 m3 = make_float2(
        s0.x + b * rv.x - sbv * P2v.x - b * sb2v * hv.x,
        s0.y + b * rv.y - sbv * P2v.y - b * sb2v * hv.y);
    int d = g_deg[w];
    float2 y;
    if (d == 0) {
        y = hv;
    } else {
        float s = lm / ((float)d + FEPS);
        y.x = (1.f - lm) * hv.x + s * m3.x;
        y.y = (1.f - lm) * hv.y + s * m3.y;
    }
    y.x = fmaxf(y.x, 0.f); y.y = fmaxf(y.y, 0.f);
    float2 xv = ld2(x + w * 64 + lane * 2);
    st2(out + w * 64 + lane * 2, make_float2(xv.x + y.x, xv.y + y.y));
}

// ---------------- launch ----------------
extern "C" void kernel_launch(void* const* d_in, const int* in_sizes, int n_in,
                              void* d_out, int out_size)
{
    const float* x  = (const float*)d_in[0];
    const int*   ei = (const int*)  d_in[1];
    const float* W  = (const float*)d_in[2];
    const float* b  = (const float*)d_in[3];
    const float* lm = (const float*)d_in[4];
    const int* src = ei;
    const int* dst = ei + EE;

    const int nodeBlocks = (NN + 255) / 256;
    const int edgeBlocks = (EE + 255) / 256;
    const int warpBlocks = (NN * 32) / 256;   // 1 warp per node, 8 warps/block

    zero_deg_kernel<<<nodeBlocks, 256>>>();
    deg_kernel<<<edgeBlocks, 256>>>(src);
    beta_kernel<<<nodeBlocks, 256>>>(lm);
    scan_kernel<<<1, 1024>>>();
    adjfill_kernel<<<edgeBlocks, 256>>>(src, dst);
    gemm_kernel<<<NN / 32, 256>>>(x, W, b);
    g1_kernel<<<warpBlocks, 256>>>(lm);
    g2_kernel<<<warpBlocks, 256>>>(lm);
    g3_kernel<<<warpBlocks, 256>>>(lm);
    g4_kernel<<<warpBlocks, 256>>>(x, lm, (float*)d_out);
}

// round 4
// speedup vs baseline: 2.3437x; 1.5096x over previous
#include <cuda_runtime.h>

#define NN 100000
#define EE 1600000
#define FEPS 1e-9f
#define NBLK 391   // (NN + 255) / 256

// ---------------- static device scratch ----------------
__device__ float g_h  [NN * 64];
__device__ float g_P1 [NN * 64];
__device__ float g_P2 [NN * 64];
__device__ float g_P3 [NN * 64];
__device__ float g_q  [NN * 64];   // q[v]  = sum_u beta_u * h[u]
__device__ float g_r  [NN * 64];   // r[v]  = sum_u beta_u * P1[u]
__device__ float g_beta[NN];
__device__ float g_sb  [NN];       // sum_u beta_u
__device__ float g_sb2 [NN];       // sum_u beta_u^2
__device__ int   g_deg [NN];
__device__ int   g_prefix[NN];
__device__ int   g_blocksum[NBLK];
__device__ int   g_blockoff[NBLK];
__device__ int   g_start[NN + 1];
__device__ int   g_cursor[NN];
__device__ int   g_adj[EE];        // in-neighbor (src) list bucketed by dst

__device__ __forceinline__ float2 ld2(const float* p) { return *(const float2*)p; }
__device__ __forceinline__ void   st2(float* p, float2 v) { *(float2*)p = v; }

// ---------------- CSR build ----------------
__global__ void zero_deg_kernel() {
    int i = blockIdx.x * blockDim.x + threadIdx.x;
    if (i < NN) g_deg[i] = 0;
}

__global__ void deg_kernel(const int* __restrict__ src) {
    int e = blockIdx.x * blockDim.x + threadIdx.x;
    if (e < EE) atomicAdd(&g_deg[src[e]], 1);
}

// Phase 1: per-block exclusive scan of deg (warp shuffle), emit block sums.
__global__ __launch_bounds__(256) void scan1_kernel() {
    __shared__ int warp_sums[8];
    int t = threadIdx.x;
    int i = blockIdx.x * 256 + t;
    int d = (i < NN) ? g_deg[i] : 0;
    int v = d;
    #pragma unroll
    for (int off = 1; off < 32; off <<= 1) {
        int n = __shfl_up_sync(0xffffffffu, v, off);
        if ((t & 31) >= off) v += n;
    }
    if ((t & 31) == 31) warp_sums[t >> 5] = v;
    __syncthreads();
    if (t < 8) {
        int s = warp_sums[t];
        #pragma unroll
        for (int off = 1; off < 8; off <<= 1) {
            int n = __shfl_up_sync(0xffu, s, off);
            if (t >= off) s += n;
        }
        warp_sums[t] = s;
    }
    __syncthreads();
    int base = (t >= 32) ? warp_sums[(t >> 5) - 1] : 0;
    int incl = v + base;
    if (i < NN) g_prefix[i] = incl - d;
    if (t == 255) g_blocksum[blockIdx.x] = incl;
}

// Phase 2: single-block scan of 391 block sums (all in smem).
__global__ __launch_bounds__(512) void scan2_kernel() {
    __shared__ int s[512];
    int t = threadIdx.x;
    int v = (t < NBLK) ? g_blocksum[t] : 0;
    s[t] = v;
    __syncthreads();
    for (int off = 1; off < 512; off <<= 1) {
        int n = (t >= off) ? s[t - off] : 0;
        __syncthreads();
        s[t] += n;
        __syncthreads();
    }
    if (t < NBLK) g_blockoff[t] = s[t] - v;
}

// Phase 3: finalize start/cursor, compute beta (fused).
__global__ void finish_kernel(const float* __restrict__ lptr) {
    int i = blockIdx.x * blockDim.x + threadIdx.x;
    if (i >= NN) return;
    int st = g_prefix[i] + g_blockoff[i >> 8];
    g_start[i] = st;
    g_cursor[i] = st;
    float lm = __ldg(lptr);
    int d = g_deg[i];
    g_beta[i] = (d == 1) ? 0.0f : lm / ((float)d - 1.0f + FEPS);
    if (i == 0) g_start[NN] = EE;
}

__global__ void adjfill_kernel(const int* __restrict__ src, const int* __restrict__ dst) {
    int e = blockIdx.x * blockDim.x + threadIdx.x;
    if (e >= EE) return;
    int v = dst[e];
    int pos = atomicAdd(&g_cursor[v], 1);
    g_adj[pos] = src[e];
}

// ---------------- h = x @ W + b ----------------
__global__ __launch_bounds__(256) void gemm_kernel(
    const float* __restrict__ x, const float* __restrict__ W, const float* __restrict__ b)
{
    __shared__ float sW[64 * 64];
    __shared__ float sx[32 * 68];
    __shared__ float sb[64];
    int t = threadIdx.x;
    #pragma unroll
    for (int i = t; i < 4096; i += 256) sW[i] = W[i];
    if (t < 64) sb[t] = b[t];
    int row0 = blockIdx.x * 32;
    const float4* xv = (const float4*)(x + row0 * 64);
    #pragma unroll
    for (int i = t; i < 512; i += 256) {
        float4 v = xv[i];
        int r = i >> 4, c4 = i & 15;
        float* d = &sx[r * 68 + c4 * 4];
        d[0] = v.x; d[1] = v.y; d[2] = v.z; d[3] = v.w;
    }
    __syncthreads();
    int r = t >> 3, c0 = (t & 7) * 8;
    float acc[8];
    #pragma unroll
    for (int j = 0; j < 8; j++) acc[j] = sb[c0 + j];
    #pragma unroll
    for (int k = 0; k < 64; k++) {
        float xk = sx[r * 68 + k];
        float4 w0 = *(const float4*)&sW[k * 64 + c0];
        float4 w1 = *(const float4*)&sW[k * 64 + c0 + 4];
        acc[0] += xk * w0.x; acc[1] += xk * w0.y; acc[2] += xk * w0.z; acc[3] += xk * w0.w;
        acc[4] += xk * w1.x; acc[5] += xk * w1.y; acc[6] += xk * w1.z; acc[7] += xk * w1.w;
    }
    float* out = &g_h[(row0 + r) * 64 + c0];
    *(float4*)out       = make_float4(acc[0], acc[1], acc[2], acc[3]);
    *(float4*)(out + 4) = make_float4(acc[4], acc[5], acc[6], acc[7]);
}

// ---------------- gather passes: one warp per node, float2 per lane ----------------

// G1: s0 = sum h[u]; s1 = sum b_u h[u]; sb, sb2; P1 = a*h + b*s0
__global__ __launch_bounds__(256) void g1_kernel(const float* __restrict__ lptr) {
    int w = (blockIdx.x * blockDim.x + threadIdx.x) >> 5;
    int lane = threadIdx.x & 31;
    if (w >= NN) return;
    int beg = g_start[w], end = g_start[w + 1];
    float2 s0 = make_float2(0.f, 0.f), s1 = make_float2(0.f, 0.f);
    float sb = 0.f, sb2 = 0.f;
    int j = beg;
    for (; j + 3 < end; j += 4) {
        int u0 = g_adj[j], u1 = g_adj[j + 1], u2 = g_adj[j + 2], u3 = g_adj[j + 3];
        float b0 = g_beta[u0], b1 = g_beta[u1], b2 = g_beta[u2], b3 = g_beta[u3];
        float2 h0 = ld2(g_h + u0 * 64 + lane * 2);
        float2 h1 = ld2(g_h + u1 * 64 + lane * 2);
        float2 h2 = ld2(g_h + u2 * 64 + lane * 2);
        float2 h3 = ld2(g_h + u3 * 64 + lane * 2);
        s0.x += (h0.x + h1.x) + (h2.x + h3.x);
        s0.y += (h0.y + h1.y) + (h2.y + h3.y);
        s1.x += b0 * h0.x + b1 * h1.x + b2 * h2.x + b3 * h3.x;
        s1.y += b0 * h0.y + b1 * h1.y + b2 * h2.y + b3 * h3.y;
        sb  += (b0 + b1) + (b2 + b3);
        sb2 += (b0 * b0 + b1 * b1) + (b2 * b2 + b3 * b3);
    }
    for (; j < end; j++) {
        int u0 = g_adj[j];
        float b0 = g_beta[u0];
        float2 h0 = ld2(g_h + u0 * 64 + lane * 2);
        s0.x += h0.x; s0.y += h0.y;
        s1.x += b0 * h0.x; s1.y += b0 * h0.y;
        sb += b0; sb2 += b0 * b0;
    }
    float lm = __ldg(lptr);
    float b = g_beta[w];
    float a = (b == 0.f) ? 1.f : (1.f - lm);
    float2 hv = ld2(g_h + w * 64 + lane * 2);
    float2 P1 = make_float2(a * hv.x + b * s0.x, a * hv.y + b * s0.y);
    st2(g_P1 + w * 64 + lane * 2, P1);
    st2(g_q  + w * 64 + lane * 2, s1);
    if (lane == 0) { g_sb[w] = sb; g_sb2[w] = sb2; }
}

// G2: s0 = sum P1[u]; s1 = sum b_u P1[u]; m1 = s0 - sb*h; P2 = a*h + b*m1
__global__ __launch_bounds__(256) void g2_kernel(const float* __restrict__ lptr) {
    int w = (blockIdx.x * blockDim.x + threadIdx.x) >> 5;
    int lane = threadIdx.x & 31;
    if (w >= NN) return;
    int beg = g_start[w], end = g_start[w + 1];
    float2 s0 = make_float2(0.f, 0.f), s1 = make_float2(0.f, 0.f);
    int j = beg;
    for (; j + 3 < end; j += 4) {
        int u0 = g_adj[j], u1 = g_adj[j + 1], u2 = g_adj[j + 2], u3 = g_adj[j + 3];
        float b0 = g_beta[u0], b1 = g_beta[u1], b2 = g_beta[u2], b3 = g_beta[u3];
        float2 p0 = ld2(g_P1 + u0 * 64 + lane * 2);
        float2 p1 = ld2(g_P1 + u1 * 64 + lane * 2);
        float2 p2 = ld2(g_P1 + u2 * 64 + lane * 2);
        float2 p3 = ld2(g_P1 + u3 * 64 + lane * 2);
        s0.x += (p0.x + p1.x) + (p2.x + p3.x);
        s0.y += (p0.y + p1.y) + (p2.y + p3.y);
        s1.x += b0 * p0.x + b1 * p1.x + b2 * p2.x + b3 * p3.x;
        s1.y += b0 * p0.y + b1 * p1.y + b2 * p2.y + b3 * p3.y;
    }
    for (; j < end; j++) {
        int u0 = g_adj[j];
        float b0 = g_beta[u0];
        float2 p0 = ld2(g_P1 + u0 * 64 + lane * 2);
        s0.x += p0.x; s0.y += p0.y;
        s1.x += b0 * p0.x; s1.y += b0 * p0.y;
    }
    float lm = __ldg(lptr);
    float b = g_beta[w];
    float a = (b == 0.f) ? 1.f : (1.f - lm);
    float sbv = g_sb[w];
    float2 hv = ld2(g_h + w * 64 + lane * 2);
    float2 m1 = make_float2(s0.x - sbv * hv.x, s0.y - sbv * hv.y);
    float2 P2 = make_float2(a * hv.x + b * m1.x, a * hv.y + b * m1.y);
    st2(g_P2 + w * 64 + lane * 2, P2);
    st2(g_r  + w * 64 + lane * 2, s1);
}

// G3: s0 = sum P2[u]; m2 = s0 + b*q - sb*P1; P3 = a*h + b*m2
__global__ __launch_bounds__(256) void g3_kernel(const float* __restrict__ lptr) {
    int w = (blockIdx.x * blockDim.x + threadIdx.x) >> 5;
    int lane = threadIdx.x & 31;
    if (w >= NN) return;
    int beg = g_start[w], end = g_start[w + 1];
    float2 s0 = make_float2(0.f, 0.f);
    int j = beg;
    for (; j + 3 < end; j += 4) {
        int u0 = g_adj[j], u1 = g_adj[j + 1], u2 = g_adj[j + 2], u3 = g_adj[j + 3];
        float2 p0 = ld2(g_P2 + u0 * 64 + lane * 2);
        float2 p1 = ld2(g_P2 + u1 * 64 + lane * 2);
        float2 p2 = ld2(g_P2 + u2 * 64 + lane * 2);
        float2 p3 = ld2(g_P2 + u3 * 64 + lane * 2);
        s0.x += (p0.x + p1.x) + (p2.x + p3.x);
        s0.y += (p0.y + p1.y) + (p2.y + p3.y);
    }
    for (; j < end; j++) {
        int u0 = g_adj[j];
        float2 p0 = ld2(g_P2 + u0 * 64 + lane * 2);
        s0.x += p0.x; s0.y += p0.y;
    }
    float lm = __ldg(lptr);
    float b = g_beta[w];
    float a = (b == 0.f) ? 1.f : (1.f - lm);
    float sbv = g_sb[w];
    float2 hv  = ld2(g_h  + w * 64 + lane * 2);
    float2 qv  = ld2(g_q  + w * 64 + lane * 2);
    float2 P1v = ld2(g_P1 + w * 64 + lane * 2);
    float2 m2 = make_float2(s0.x + b * qv.x - sbv * P1v.x,
                            s0.y + b * qv.y - sbv * P1v.y);
    float2 P3 = make_float2(a * hv.x + b * m2.x, a * hv.y + b * m2.y);
    st2(g_P3 + w * 64 + lane * 2, P3);
}

// G4: s0 = sum P3[u]; m3 = s0 + b*r - sb*P2 - b*sb2*h; out = x + relu(final)
__global__ __launch_bounds__(256) void g4_kernel(
    const float* __restrict__ x, const float* __restrict__ lptr, float* __restrict__ out)
{
    int w = (blockIdx.x * blockDim.x + threadIdx.x) >> 5;
    int lane = threadIdx.x & 31;
    if (w >= NN) return;
    int beg = g_start[w], end = g_start[w + 1];
    float2 s0 = make_float2(0.f, 0.f);
    int j = beg;
    for (; j + 3 < end; j += 4) {
        int u0 = g_adj[j], u1 = g_adj[j + 1], u2 = g_adj[j + 2], u3 = g_adj[j + 3];
        float2 p0 = ld2(g_P3 + u0 * 64 + lane * 2);
        float2 p1 = ld2(g_P3 + u1 * 64 + lane * 2);
        float2 p2 = ld2(g_P3 + u2 * 64 + lane * 2);
        float2 p3 = ld2(g_P3 + u3 * 64 + lane * 2);
        s0.x += (p0.x + p1.x) + (p2.x + p3.x);
        s0.y += (p0.y + p1.y) + (p2.y + p3.y);
    }
    for (; j < end; j++) {
        int u0 = g_adj[j];
        float2 p0 = ld2(g_P3 + u0 * 64 + lane * 2);
        s0.x += p0.x; s0.y += p0.y;
    }
    float lm = __ldg(lptr);
    float b = g_beta[w];
    float sbv = g_sb[w], sb2v = g_sb2[w];
    float2 hv  = ld2(g_h  + w * 64 + lane * 2);
    float2 rv  = ld2(g_r  + w * 64 + lane * 2);
    float2 P2v = ld2(g_P2 + w * 64 + lane * 2);
    float2 m3 = make_float2(
        s0.x + b * rv.x - sbv * P2v.x - b * sb2v * hv.x,
        s0.y + b * rv.y - sbv * P2v.y - b * sb2v * hv.y);
    int d = g_deg[w];
    float2 y;
    if (d == 0) {
        y = hv;
    } else {
        float s = lm / ((float)d + FEPS);
        y.x = (1.f - lm) * hv.x + s * m3.x;
        y.y = (1.f - lm) * hv.y + s * m3.y;
    }
    y.x = fmaxf(y.x, 0.f); y.y = fmaxf(y.y, 0.f);
    float2 xv = ld2(x + w * 64 + lane * 2);
    st2(out + w * 64 + lane * 2, make_float2(xv.x + y.x, xv.y + y.y));
}

// ---------------- launch ----------------
extern "C" void kernel_launch(void* const* d_in, const int* in_sizes, int n_in,
                              void* d_out, int out_size)
{
    const float* x  = (const float*)d_in[0];
    const int*   ei = (const int*)  d_in[1];
    const float* W  = (const float*)d_in[2];
    const float* b  = (const float*)d_in[3];
    const float* lm = (const float*)d_in[4];
    const int* src = ei;
    const int* dst = ei + EE;

    const int nodeBlocks = (NN + 255) / 256;   // 391
    const int edgeBlocks = (EE + 255) / 256;
    const int warpBlocks = (NN * 32) / 256;    // 1 warp per node

    zero_deg_kernel<<<nodeBlocks, 256>>>();
    deg_kernel<<<edgeBlocks, 256>>>(src);
    scan1_kernel<<<NBLK, 256>>>();
    scan2_kernel<<<1, 512>>>();
    finish_kernel<<<nodeBlocks, 256>>>(lm);
    adjfill_kernel<<<edgeBlocks, 256>>>(src, dst);
    gemm_kernel<<<NN / 32, 256>>>(x, W, b);
    g1_kernel<<<warpBlocks, 256>>>(lm);
    g2_kernel<<<warpBlocks, 256>>>(lm);
    g3_kernel<<<warpBlocks, 256>>>(lm);
    g4_kernel<<<warpBlocks, 256>>>(x, lm, (float*)d_out);
}